// round 6
// baseline (speedup 1.0000x reference)
#include <cuda_runtime.h>
#include <cstdint>

// FieldAwareFM: B=16384, F=10 fields, D=8.
// y[b] = b_lin + sum_f w[xoff[b,f]] + sum_{f<g} <emb[f, xoff[b,g]], emb[g, xoff[b,f]]>
//
// Kernel 1 packs small fields (4..9, 8610 cols) into per-column 9-row blocks
// (+ linear w) -> the rows keyed by one small-field index live in 3 lines.
// Kernel 2: one warp per sample-iteration, 90 (pair,half) tasks, pair order
// g-DESC for A-side line sharing. Grid is one resident wave (888 blocks =
// 6/SM); each warp loops over ~2.3 samples so the pair-decode (sqrt) and all
// task constants are hoisted out of the per-sample work.

#define BATCH      16384
#define NUM_FIELDS 10
#define FACTOR_DIM 8
#define INPUT_DIM  188610
#define NPAIRS     45
#define NPACKCOLS  8610
#define BLK_F      80          // floats per packed block (9*8 + w + pad)
#define BLK_B      (BLK_F*4)   // 320 bytes

#define GRID_MAIN  888         // 6 blocks/SM on 148 SMs, exactly resident
#define TOT_WARPS  (GRID_MAIN * 8)

__constant__ int c_off[NUM_FIELDS] = {
    0, 100000, 150000, 170000, 180000, 185000, 187000, 188000, 188500, 188600
};
__constant__ int c_pb[6] = { 0, 5000, 7000, 8000, 8500, 8600 };  // fields 4..9

__device__ __align__(128) float g_pack[NPACKCOLS * BLK_F];

// ---------------- pack kernel ----------------
__global__ __launch_bounds__(256) void pack_kernel(
    const float* __restrict__ w,
    const float* __restrict__ emb)
{
    int tid = blockIdx.x * blockDim.x + threadIdx.x;   // [0, 8610*20)
    if (tid >= NPACKCOLS * 20) return;
    int jp = tid / 20;
    int u  = tid % 20;
    int c4 = (jp >= 5000) + (jp >= 7000) + (jp >= 8000) + (jp >= 8500) + (jp >= 8600);
    int c  = 4 + c4;
    int col = c_off[c] + (jp - c_pb[c4]);

    if (u < 18) {
        int s = u >> 1, part = u & 1;
        int f = s + (s >= c);
        const float4 v = *reinterpret_cast<const float4*>(
            emb + ((size_t)f * INPUT_DIM + (size_t)col) * FACTOR_DIM + part * 4);
        *reinterpret_cast<float4*>(g_pack + (size_t)jp * BLK_F + s * 8 + part * 4) = v;
    } else if (u == 18) {
        g_pack[(size_t)jp * BLK_F + 72] = w[col];
    }
}

// ---------------- main kernel ----------------
__global__ __launch_bounds__(256, 6) void ffm_kernel(
    const int*   __restrict__ x,       // (B, 10) int32
    const float* __restrict__ w,       // (INPUT_DIM,)
    const float* __restrict__ blin,    // scalar
    const float* __restrict__ emb,     // (10, INPUT_DIM, 8)
    float*       __restrict__ out)     // (B,)
{
    const unsigned FULL = 0xFFFFFFFFu;
    int gw   = (blockIdx.x * blockDim.x + threadIdx.x) >> 5;  // global warp id
    int lane = threadIdx.x & 31;

    // ---- hoisted per-task constants (loop-invariant per warp) ----
    // Pairs sorted g-DESC then f-ASC; exact fp32 sqrt decode (perfect squares).
    int enc[3];                       // f | g<<8 | valid<<16
    #pragma unroll
    for (int k = 0; k < 3; k++) {
        int t = lane + 32 * k;
        int f = 0, g = 1, vld = 0;
        if (t < 2 * NPAIRS) {
            int   p = t >> 1;
            int   r = NPAIRS - p;
            float s = sqrtf((float)(8 * r + 1));
            g = (int)ceilf((s - 1.0f) * 0.5f);
            f = p - NPAIRS + (g * (g + 1)) / 2;
            vld = 1;
        }
        enc[k] = f | (g << 8) | (vld << 16);
    }
    const int   partB = (lane & 1) << 4;     // 16B half (t&1 == lane&1)
    const char* pk = (const char*)g_pack;
    const char* eb = (const char*)emb;
    const float bl = blin[0];

    for (int b = gw; b < BATCH; b += TOT_WARPS) {
        // Lane f (<10) owns field f. V = byte key:
        //   packed (f>=4): V = ~blockByteBase (negative); raw: V = xoff*32.
        int   V   = 0;
        float acc = 0.0f;
        if (lane < NUM_FIELDS) {
            int xr = x[b * NUM_FIELDS + lane];
            if (lane >= 4) {
                int pbb = (c_pb[lane - 4] + xr) * BLK_B;
                V   = ~pbb;
                acc = *(const float*)(pk + pbb + 288);    // w folded into block
            } else {
                V   = (xr + c_off[lane]) * 32;
                acc = w[xr + c_off[lane]];
            }
        }

        float4 va[3], vb[3];
        #pragma unroll
        for (int k = 0; k < 3; k++) {
            int f = enc[k] & 0xff;
            int g = (enc[k] >> 8) & 0xff;

            int vg = __shfl_sync(FULL, V, g);   // key of A row: emb[f, x_g]
            int vf = __shfl_sync(FULL, V, f);   // key of B row: emb[g, x_f]

            const char* pA = (vg < 0) ? (pk + (~vg) + f * 32)
                                      : (eb + (unsigned)(f * (INPUT_DIM * 32)) + (unsigned)vg);
            const char* pB = (vf < 0) ? (pk + (~vf) + (g - 1) * 32)
                                      : (eb + (unsigned)(g * (INPUT_DIM * 32)) + (unsigned)vf);

            if (enc[k] >> 16) {
                va[k] = *(const float4*)(pA + partB);
                vb[k] = *(const float4*)(pB + partB);
            } else {
                va[k] = make_float4(0.f, 0.f, 0.f, 0.f);
                vb[k] = make_float4(0.f, 0.f, 0.f, 0.f);
            }
        }

        #pragma unroll
        for (int k = 0; k < 3; k++) {
            acc += va[k].x * vb[k].x + va[k].y * vb[k].y
                 + va[k].z * vb[k].z + va[k].w * vb[k].w;
        }

        #pragma unroll
        for (int o = 16; o > 0; o >>= 1)
            acc += __shfl_xor_sync(FULL, acc, o);

        if (lane == 0)
            out[b] = acc + bl;
    }
}

extern "C" void kernel_launch(void* const* d_in, const int* in_sizes, int n_in,
                              void* d_out, int out_size) {
    const int*   x    = (const int*)  d_in[0];
    const float* w    = (const float*)d_in[1];
    const float* blin = (const float*)d_in[2];
    const float* emb  = (const float*)d_in[3];
    float* out = (float*)d_out;

    const int pack_threads = 256;
    const int pack_blocks  = (NPACKCOLS * 20 + pack_threads - 1) / pack_threads;
    pack_kernel<<<pack_blocks, pack_threads>>>(w, emb);

    ffm_kernel<<<GRID_MAIN, 256>>>(x, w, blin, emb, out);
}